// round 13
// baseline (speedup 1.0000x reference)
#include <cuda_runtime.h>
#include <cuda_bf16.h>
#include <cstdint>

#define NG 64
#define NC 32
#define LL 128
#define DD 64
#define HH 128
#define NCLASS 10
#define BTOT 2048          // G*C
#define NGATES 512         // 4*H

__device__ float g_rep[BTOT * HH];   // sum_t h (allocation-free scratch)

typedef unsigned long long u64;

__device__ __forceinline__ float tanh_fast(float x) {
    float r;
    asm("tanh.approx.f32 %0, %1;" : "=f"(r) : "f"(x));
    return r;
}
__device__ __forceinline__ float sig_fast(float x) {
    return fmaf(0.5f, tanh_fast(0.5f * x), 0.5f);
}
__device__ __forceinline__ uint32_t pack_bf2(float lo, float hi) {
    __nv_bfloat162 v = __floats2bfloat162_rn(lo, hi);   // .x = lo
    return *(uint32_t*)&v;
}

#define MMA_BF16(acc, a0, a1, a2, a3, bb0, bb1) \
    asm("mma.sync.aligned.m16n8k16.row.col.f32.bf16.bf16.f32 " \
        "{%0,%1,%2,%3}, {%4,%5,%6,%7}, {%8,%9}, {%0,%1,%2,%3};" \
        : "+f"((acc)[0]), "+f"((acc)[1]), "+f"((acc)[2]), "+f"((acc)[3]) \
        : "r"(a0), "r"(a1), "r"(a2), "r"(a3), "r"(bb0), "r"(bb1))

// ============================================================================
// Fused LSTM (input GEMM + recurrence), round-12 base + ONE change:
// the x-GEMM for step t+1 is hoisted to the end of iteration t (after the
// h STS), so its 12 LDS + 16 MMAs leave the post-barrier critical path.
// Plain __syncthreads kept (round 10's named-barrier pair is NOT reintroduced).
// x chunk staging moves to t%16==14 for chunk (t+2)/16 (one barrier phase
// between STS and first LDS; buffer parity has no WAR overlap).
// 128 CTAs x 512 threads; warp w: units 8w..8w+7 x 4 gates; W_hh in regs.
// ============================================================================
#define LTH 512
#define HFQ_O 0                    // [2][8][32] uint4      (8 KB)
#define XFQ_O 512                  // [2][16][4][32] uint4  (64 KB)
#define WIFQ_O (512 + 4096)        // [16][4][2][32] uint4  (64 KB)
#define LSMQ (WIFQ_O + 4096)
#define LSM_BYTES (LSMQ * 16)      // 139264 B

__device__ __forceinline__ void stage_chunk(uint4* xfq, const float* x,
                                            int b0, int chunk,
                                            int s_tl, int s_kk2, int s_j) {
    int cb = chunk & 1;
    const float* p0 = x + (((size_t)(b0 + s_j) * LL) + (chunk * 16 + s_tl)) * DD + s_kk2 * 16;
    const float* p1 = p0 + (size_t)8 * LL * DD;
    float4 r0a = *(const float4*)p0,       r0b = *(const float4*)(p0 + 4);
    float4 r0c = *(const float4*)(p0 + 8), r0d = *(const float4*)(p0 + 12);
    float4 r1a = *(const float4*)p1,       r1b = *(const float4*)(p1 + 4);
    float4 r1c = *(const float4*)(p1 + 8), r1d = *(const float4*)(p1 + 12);
    uint4* dst = &xfq[((cb * 16 + s_tl) * 4 + s_kk2) * 32 + 4 * s_j];
    dst[0] = make_uint4(pack_bf2(r0a.x, r0a.y), pack_bf2(r1a.x, r1a.y),
                        pack_bf2(r0c.x, r0c.y), pack_bf2(r1c.x, r1c.y));
    dst[1] = make_uint4(pack_bf2(r0a.z, r0a.w), pack_bf2(r1a.z, r1a.w),
                        pack_bf2(r0c.z, r0c.w), pack_bf2(r1c.z, r1c.w));
    dst[2] = make_uint4(pack_bf2(r0b.x, r0b.y), pack_bf2(r1b.x, r1b.y),
                        pack_bf2(r0d.x, r0d.y), pack_bf2(r1d.x, r1d.y));
    dst[3] = make_uint4(pack_bf2(r0b.z, r0b.w), pack_bf2(r1b.z, r1b.w),
                        pack_bf2(r0d.z, r0d.w), pack_bf2(r1d.z, r1d.w));
}

__global__ void __launch_bounds__(LTH, 1)
lstm_fused(const float* __restrict__ x, const float* __restrict__ W_ih,
           const float* __restrict__ W_hh,
           const float* __restrict__ b_ih, const float* __restrict__ b_hh) {
    extern __shared__ uint4 smq[];
    uint4* hfq  = smq + HFQ_O;    // [(buf*8+kk)*32 + lane]
    uint4* xfq  = smq + XFQ_O;    // [((buf*16+tl)*4+kk2)*32 + lane]
    uint4* wifq = smq + WIFQ_O;   // [((w*4+kk2)*2+p)*32 + lane]

    int tid = threadIdx.x, lane = tid & 31, w = tid >> 5;   // w in [0,16)
    int t4 = lane >> 2, tm4 = lane & 3;
    int b0 = blockIdx.x * 16;
    int colbase = 8 * w + 2 * tm4;    // unit pair (colbase, colbase+1)

    // W_hh bf16 B-fragments -> registers (one-time). Frag col n = t4.
    uint32_t wb0[8][4], wb1[8][4];
#pragma unroll
    for (int kk = 0; kk < 8; kk++)
#pragma unroll
        for (int g = 0; g < 4; g++) {
            int row = g * HH + 8 * w + t4;
            float2 lo2 = *(const float2*)&W_hh[row * HH + kk * 16 + 2 * tm4];
            float2 hi2 = *(const float2*)&W_hh[row * HH + kk * 16 + 2 * tm4 + 8];
            wb0[kk][g] = pack_bf2(lo2.x, lo2.y);
            wb1[kk][g] = pack_bf2(hi2.x, hi2.y);
        }

    // W_ih bf16 B-fragments -> smem (warp-private region; K=64 -> 4 kk2)
#pragma unroll
    for (int kk2 = 0; kk2 < 4; kk2++) {
        uint32_t bb[4][2];
#pragma unroll
        for (int g = 0; g < 4; g++) {
            int row = g * HH + 8 * w + t4;
            float2 lo2 = *(const float2*)&W_ih[row * DD + kk2 * 16 + 2 * tm4];
            float2 hi2 = *(const float2*)&W_ih[row * DD + kk2 * 16 + 2 * tm4 + 8];
            bb[g][0] = pack_bf2(lo2.x, lo2.y);
            bb[g][1] = pack_bf2(hi2.x, hi2.y);
        }
        wifq[((w * 4 + kk2) * 2 + 0) * 32 + lane] =
            make_uint4(bb[0][0], bb[0][1], bb[1][0], bb[1][1]);
        wifq[((w * 4 + kk2) * 2 + 1) * 32 + lane] =
            make_uint4(bb[2][0], bb[2][1], bb[3][0], bb[3][1]);
    }
    hfq[tid] = make_uint4(0, 0, 0, 0);   // zero h fragments (both buffers)

    const int kkp = w >> 1;              // producer h-store coords
    const int wordoff = 8 * (w & 1);
    const int s_tl = tid >> 5, s_kk2 = (tid >> 3) & 3, s_j = tid & 7;  // x staging

    // Stage x chunk 0 (steps 0..15)
    stage_chunk(xfq, x, b0, 0, s_tl, s_kk2, s_j);

    float2 bias2[4];
#pragma unroll
    for (int g = 0; g < 4; g++) {
        int c = g * HH + colbase;
        bias2[g] = make_float2(b_ih[c] + b_hh[c], b_ih[c + 1] + b_hh[c + 1]);
    }
    float cst[4], hsum[4];
#pragma unroll
    for (int k = 0; k < 4; k++) { cst[k] = 0.f; hsum[k] = 0.f; }

    __syncthreads();   // chunk 0 + hfq zeros + wifq visible

    // Prime: x-GEMM for t=0 into acc
    float acc[4][4];
#pragma unroll
    for (int g = 0; g < 4; g++)
#pragma unroll
        for (int q = 0; q < 4; q++) acc[g][q] = 0.f;
#pragma unroll
    for (int kk2 = 0; kk2 < 4; kk2++) {
        uint4 aq = xfq[(0 * 4 + kk2) * 32 + lane];
        uint4 q0 = wifq[((w * 4 + kk2) * 2 + 0) * 32 + lane];
        uint4 q1 = wifq[((w * 4 + kk2) * 2 + 1) * 32 + lane];
        MMA_BF16(acc[0], aq.x, aq.y, aq.z, aq.w, q0.x, q0.y);
        MMA_BF16(acc[1], aq.x, aq.y, aq.z, aq.w, q0.z, q0.w);
        MMA_BF16(acc[2], aq.x, aq.y, aq.z, aq.w, q1.x, q1.y);
        MMA_BF16(acc[3], aq.x, aq.y, aq.z, aq.w, q1.z, q1.w);
    }

    int cur = 0;
#pragma unroll 1
    for (int t = 0; t < LL; t++) {
        __syncthreads();   // h[cur] (prev step) + chunk staged last iter visible

        // Recurrence: h_{t-1} @ W_hh^T (W_hh in registers); acc already holds
        // the x contribution for step t (computed at end of previous iter)
#pragma unroll
        for (int kk = 0; kk < 8; kk++) {
            uint4 aq = hfq[(cur * 8 + kk) * 32 + lane];
            MMA_BF16(acc[0], aq.x, aq.y, aq.z, aq.w, wb0[kk][0], wb1[kk][0]);
            MMA_BF16(acc[1], aq.x, aq.y, aq.z, aq.w, wb0[kk][1], wb1[kk][1]);
            MMA_BF16(acc[2], aq.x, aq.y, aq.z, aq.w, wb0[kk][2], wb1[kk][2]);
            MMA_BF16(acc[3], aq.x, aq.y, aq.z, aq.w, wb0[kk][3], wb1[kk][3]);
        }

        int nxt = cur ^ 1;
        uint32_t hv[2];
#pragma unroll
        for (int rs = 0; rs < 2; rs++) {
            int q = rs * 2;   // C-frag: q0,q1 = row t4; q2,q3 = row t4+8
            float iA = sig_fast(acc[0][q]     + bias2[0].x);
            float iB = sig_fast(acc[0][q + 1] + bias2[0].y);
            float fA = sig_fast(acc[1][q]     + bias2[1].x);
            float fB = sig_fast(acc[1][q + 1] + bias2[1].y);
            float gA = tanh_fast(acc[2][q]     + bias2[2].x);
            float gB = tanh_fast(acc[2][q + 1] + bias2[2].y);
            float oA = sig_fast(acc[3][q]     + bias2[3].x);
            float oB = sig_fast(acc[3][q + 1] + bias2[3].y);
            int s = rs * 2;
            float cA = fmaf(fA, cst[s],     iA * gA);
            float cB = fmaf(fB, cst[s + 1], iB * gB);
            cst[s] = cA; cst[s + 1] = cB;
            float hA = oA * tanh_fast(cA);
            float hB = oB * tanh_fast(cB);
            hsum[s] += hA; hsum[s + 1] += hB;
            hv[rs] = pack_bf2(hA, hB);
        }
        {   // one STS.64: this thread's h unit-pair, in A-fragment layout
            char* p = (char*)&hfq[(nxt * 8 + kkp) * 32 + lane] + wordoff;
            u64 pp;
            asm("mov.b64 %0, {%1, %2};" : "=l"(pp) : "r"(hv[0]), "r"(hv[1]));
            asm volatile("st.shared.b64 [%0], %1;"
                         :: "l"(__cvta_generic_to_shared(p)), "l"(pp) : "memory");
        }

        // Stage chunk (t+2)/16 two steps early (one barrier phase before use)
        if ((t & 15) == 14 && t + 2 < LL)
            stage_chunk(xfq, x, b0, (t + 2) >> 4, s_tl, s_kk2, s_j);

        // x-GEMM for step t+1 (phase-stable operands; off the post-barrier
        // critical path — early warps run this while stragglers drain)
        if (t + 1 < LL) {
#pragma unroll
            for (int g = 0; g < 4; g++)
#pragma unroll
                for (int q = 0; q < 4; q++) acc[g][q] = 0.f;
            int cb = ((t + 1) >> 4) & 1, tl = (t + 1) & 15;
#pragma unroll
            for (int kk2 = 0; kk2 < 4; kk2++) {
                uint4 aq = xfq[((cb * 16 + tl) * 4 + kk2) * 32 + lane];
                uint4 q0 = wifq[((w * 4 + kk2) * 2 + 0) * 32 + lane];
                uint4 q1 = wifq[((w * 4 + kk2) * 2 + 1) * 32 + lane];
                MMA_BF16(acc[0], aq.x, aq.y, aq.z, aq.w, q0.x, q0.y);
                MMA_BF16(acc[1], aq.x, aq.y, aq.z, aq.w, q0.z, q0.w);
                MMA_BF16(acc[2], aq.x, aq.y, aq.z, aq.w, q1.x, q1.y);
                MMA_BF16(acc[3], aq.x, aq.y, aq.z, aq.w, q1.z, q1.w);
            }
        }
        cur = nxt;
    }

#pragma unroll
    for (int rs = 0; rs < 2; rs++) {
        int b = b0 + t4 + 8 * rs;
        *(float2*)&g_rep[b * HH + colbase] = make_float2(hsum[rs * 2], hsum[rs * 2 + 1]);
    }
}

// ============================================================================
// Kernel 2: per-graph mean over cycles, classifier, log_softmax.
// 256 threads: cycle-split partial sums halve the serial LDG chain.
// ============================================================================
__global__ void cls_kernel(const float* __restrict__ W_cls, const float* __restrict__ b_cls,
                           float* __restrict__ out) {
    __shared__ float part[2][HH];
    __shared__ float mean_s[HH];
    __shared__ float lg[NCLASS];
    int g = blockIdx.x, tid = threadIdx.x;
    int h = tid & 127, half = tid >> 7;
    float s = 0.f;
#pragma unroll
    for (int c = 0; c < 16; c++)
        s += g_rep[(g * NC + half * 16 + c) * HH + h];
    part[half][h] = s;
    __syncthreads();
    if (tid < HH) mean_s[tid] = (part[0][tid] + part[1][tid]) * (1.0f / NC);
    __syncthreads();
    if (tid < NCLASS) {
        float d = b_cls[tid];
        for (int hh = 0; hh < HH; hh++)
            d = fmaf(mean_s[hh], W_cls[tid * HH + hh], d);
        lg[tid] = d;
    }
    __syncthreads();
    if (tid == 0) {
        float mx = lg[0];
        for (int n = 1; n < NCLASS; n++) mx = fmaxf(mx, lg[n]);
        float sum = 0.f;
        for (int n = 0; n < NCLASS; n++) sum += expf(lg[n] - mx);
        float l = logf(sum);
        for (int n = 0; n < NCLASS; n++)
            out[g * NCLASS + n] = lg[n] - mx - l;
    }
}

extern "C" void kernel_launch(void* const* d_in, const int* in_sizes, int n_in,
                              void* d_out, int out_size) {
    (void)in_sizes; (void)n_in; (void)out_size;
    const float* x     = (const float*)d_in[0];  // cycle_reps [64,32,128,64]
    const float* W_ih  = (const float*)d_in[1];  // [512,64]
    const float* W_hh  = (const float*)d_in[2];  // [512,128]
    const float* b_ih  = (const float*)d_in[3];  // [512]
    const float* b_hh  = (const float*)d_in[4];  // [512]
    const float* W_cls = (const float*)d_in[5];  // [10,128]
    const float* b_cls = (const float*)d_in[6];  // [10]

    cudaFuncSetAttribute(lstm_fused, cudaFuncAttributeMaxDynamicSharedMemorySize, LSM_BYTES);
    lstm_fused<<<128, LTH, LSM_BYTES>>>(x, W_ih, W_hh, b_ih, b_hh);
    cls_kernel<<<NG, 256>>>(W_cls, b_cls, (float*)d_out);
}

// round 14
// speedup vs baseline: 1.1758x; 1.1758x over previous
#include <cuda_runtime.h>
#include <cuda_bf16.h>
#include <cstdint>

#define NG 64
#define NC 32
#define LL 128
#define DD 64
#define HH 128
#define NCLASS 10
#define BTOT 2048          // G*C
#define NGATES 512         // 4*H

__device__ float g_rep[BTOT * HH];   // sum_t h (allocation-free scratch)
__device__ int g_cnt[NG];            // per-graph arrival counters (self-resetting)

typedef unsigned long long u64;

__device__ __forceinline__ float tanh_fast(float x) {
    float r;
    asm("tanh.approx.f32 %0, %1;" : "=f"(r) : "f"(x));
    return r;
}
__device__ __forceinline__ float sig_fast(float x) {
    return fmaf(0.5f, tanh_fast(0.5f * x), 0.5f);
}
__device__ __forceinline__ uint32_t pack_bf2(float lo, float hi) {
    __nv_bfloat162 v = __floats2bfloat162_rn(lo, hi);   // .x = lo
    return *(uint32_t*)&v;
}

#define MMA_BF16(acc, a0, a1, a2, a3, bb0, bb1) \
    asm("mma.sync.aligned.m16n8k16.row.col.f32.bf16.bf16.f32 " \
        "{%0,%1,%2,%3}, {%4,%5,%6,%7}, {%8,%9}, {%0,%1,%2,%3};" \
        : "+f"((acc)[0]), "+f"((acc)[1]), "+f"((acc)[2]), "+f"((acc)[3]) \
        : "r"(a0), "r"(a1), "r"(a2), "r"(a3), "r"(bb0), "r"(bb1))

// ============================================================================
// Fused LSTM (input GEMM + recurrence) — step loop EXACTLY as round 12 (the
// proven 182us configuration; every loop restructure in R10/R11/R13 cost
// ~27us). ONE new thing: the classifier is fused into the kernel TAIL.
// Each graph (32 batches) spans 2 CTAs; after g_rep stores, CTAs arrive on a
// per-graph atomic counter; the second arrival computes mean + classifier +
// log_softmax for its graph (work hidden in the tail — 128 CTAs / 148 SMs)
// and resets the counter for the next graph replay. Deterministic: cls math
// is done by exactly one CTA in fixed loop order.
// ============================================================================
#define LTH 512
#define HFQ_O 0                    // [2][8][32] uint4      (8 KB)
#define XFQ_O 512                  // [2][16][4][32] uint4  (64 KB)
#define WIFQ_O (512 + 4096)        // [16][4][2][32] uint4  (64 KB)
#define LSMQ (WIFQ_O + 4096)
#define LSM_BYTES (LSMQ * 16)      // 139264 B

__global__ void __launch_bounds__(LTH, 1)
lstm_fused(const float* __restrict__ x, const float* __restrict__ W_ih,
           const float* __restrict__ W_hh,
           const float* __restrict__ b_ih, const float* __restrict__ b_hh,
           const float* __restrict__ W_cls, const float* __restrict__ b_cls,
           float* __restrict__ out) {
    extern __shared__ uint4 smq[];
    uint4* hfq  = smq + HFQ_O;    // [(buf*8+kk)*32 + lane]
    uint4* xfq  = smq + XFQ_O;    // [((buf*16+tl)*4+kk2)*32 + lane]
    uint4* wifq = smq + WIFQ_O;   // [((w*4+kk2)*2+p)*32 + lane]

    int tid = threadIdx.x, lane = tid & 31, w = tid >> 5;   // w in [0,16)
    int t4 = lane >> 2, tm4 = lane & 3;
    int b0 = blockIdx.x * 16;
    int colbase = 8 * w + 2 * tm4;    // unit pair (colbase, colbase+1)

    // W_hh bf16 B-fragments -> registers (one-time). Frag col n = t4.
    uint32_t wb0[8][4], wb1[8][4];
#pragma unroll
    for (int kk = 0; kk < 8; kk++)
#pragma unroll
        for (int g = 0; g < 4; g++) {
            int row = g * HH + 8 * w + t4;
            float2 lo2 = *(const float2*)&W_hh[row * HH + kk * 16 + 2 * tm4];
            float2 hi2 = *(const float2*)&W_hh[row * HH + kk * 16 + 2 * tm4 + 8];
            wb0[kk][g] = pack_bf2(lo2.x, lo2.y);
            wb1[kk][g] = pack_bf2(hi2.x, hi2.y);
        }

    // W_ih bf16 B-fragments -> smem (warp-private region; K=64 -> 4 kk2)
#pragma unroll
    for (int kk2 = 0; kk2 < 4; kk2++) {
        uint32_t bb[4][2];
#pragma unroll
        for (int g = 0; g < 4; g++) {
            int row = g * HH + 8 * w + t4;
            float2 lo2 = *(const float2*)&W_ih[row * DD + kk2 * 16 + 2 * tm4];
            float2 hi2 = *(const float2*)&W_ih[row * DD + kk2 * 16 + 2 * tm4 + 8];
            bb[g][0] = pack_bf2(lo2.x, lo2.y);
            bb[g][1] = pack_bf2(hi2.x, hi2.y);
        }
        wifq[((w * 4 + kk2) * 2 + 0) * 32 + lane] =
            make_uint4(bb[0][0], bb[0][1], bb[1][0], bb[1][1]);
        wifq[((w * 4 + kk2) * 2 + 1) * 32 + lane] =
            make_uint4(bb[2][0], bb[2][1], bb[3][0], bb[3][1]);
    }
    hfq[tid] = make_uint4(0, 0, 0, 0);   // zero h fragments (both buffers)

    const int kkp = w >> 1;              // producer h-store coords
    const int wordoff = 8 * (w & 1);
    const int s_tl = tid >> 5, s_kk2 = (tid >> 3) & 3, s_j = tid & 7;  // x staging

    float2 bias2[4];
#pragma unroll
    for (int g = 0; g < 4; g++) {
        int c = g * HH + colbase;
        bias2[g] = make_float2(b_ih[c] + b_hh[c], b_ih[c + 1] + b_hh[c + 1]);
    }
    float cst[4], hsum[4];
#pragma unroll
    for (int k = 0; k < 4; k++) { cst[k] = 0.f; hsum[k] = 0.f; }

    int cur = 0;
#pragma unroll 1
    for (int t = 0; t < LL; t++) {
        if ((t & 15) == 0) {
            // Stage x A-fragments for steps t..t+15 into buffer (t>>4)&1.
            int cb = (t >> 4) & 1;
            const float* p0 = x + (((size_t)(b0 + s_j) * LL) + (t + s_tl)) * DD + s_kk2 * 16;
            const float* p1 = p0 + (size_t)8 * LL * DD;
            float4 r0a = *(const float4*)p0,       r0b = *(const float4*)(p0 + 4);
            float4 r0c = *(const float4*)(p0 + 8), r0d = *(const float4*)(p0 + 12);
            float4 r1a = *(const float4*)p1,       r1b = *(const float4*)(p1 + 4);
            float4 r1c = *(const float4*)(p1 + 8), r1d = *(const float4*)(p1 + 12);
            uint4* dst = &xfq[((cb * 16 + s_tl) * 4 + s_kk2) * 32 + 4 * s_j];
            dst[0] = make_uint4(pack_bf2(r0a.x, r0a.y), pack_bf2(r1a.x, r1a.y),
                                pack_bf2(r0c.x, r0c.y), pack_bf2(r1c.x, r1c.y));
            dst[1] = make_uint4(pack_bf2(r0a.z, r0a.w), pack_bf2(r1a.z, r1a.w),
                                pack_bf2(r0c.z, r0c.w), pack_bf2(r1c.z, r1c.w));
            dst[2] = make_uint4(pack_bf2(r0b.x, r0b.y), pack_bf2(r1b.x, r1b.y),
                                pack_bf2(r0d.x, r0d.y), pack_bf2(r1d.x, r1d.y));
            dst[3] = make_uint4(pack_bf2(r0b.z, r0b.w), pack_bf2(r1b.z, r1b.w),
                                pack_bf2(r0d.z, r0d.w), pack_bf2(r1d.z, r1d.w));
        }

        __syncthreads();   // h[cur] stores (prev step) + xfq chunk visible

        float acc[4][4];
#pragma unroll
        for (int g = 0; g < 4; g++)
#pragma unroll
            for (int q = 0; q < 4; q++) acc[g][q] = 0.f;

        // Recurrence: h_{t-1} @ W_hh^T (W_hh in registers)
#pragma unroll
        for (int kk = 0; kk < 8; kk++) {
            uint4 aq = hfq[(cur * 8 + kk) * 32 + lane];
            MMA_BF16(acc[0], aq.x, aq.y, aq.z, aq.w, wb0[kk][0], wb1[kk][0]);
            MMA_BF16(acc[1], aq.x, aq.y, aq.z, aq.w, wb0[kk][1], wb1[kk][1]);
            MMA_BF16(acc[2], aq.x, aq.y, aq.z, aq.w, wb0[kk][2], wb1[kk][2]);
            MMA_BF16(acc[3], aq.x, aq.y, aq.z, aq.w, wb0[kk][3], wb1[kk][3]);
        }
        // Input GEMM: x[:,t,:] @ W_ih^T (fused into same accumulators)
        {
            int cb = (t >> 4) & 1, tl = t & 15;
#pragma unroll
            for (int kk2 = 0; kk2 < 4; kk2++) {
                uint4 aq = xfq[((cb * 16 + tl) * 4 + kk2) * 32 + lane];
                uint4 q0 = wifq[((w * 4 + kk2) * 2 + 0) * 32 + lane];
                uint4 q1 = wifq[((w * 4 + kk2) * 2 + 1) * 32 + lane];
                MMA_BF16(acc[0], aq.x, aq.y, aq.z, aq.w, q0.x, q0.y);
                MMA_BF16(acc[1], aq.x, aq.y, aq.z, aq.w, q0.z, q0.w);
                MMA_BF16(acc[2], aq.x, aq.y, aq.z, aq.w, q1.x, q1.y);
                MMA_BF16(acc[3], aq.x, aq.y, aq.z, aq.w, q1.z, q1.w);
            }
        }

        int nxt = cur ^ 1;
        uint32_t hv[2];
#pragma unroll
        for (int rs = 0; rs < 2; rs++) {
            int q = rs * 2;   // C-frag: q0,q1 = row t4; q2,q3 = row t4+8
            float iA = sig_fast(acc[0][q]     + bias2[0].x);
            float iB = sig_fast(acc[0][q + 1] + bias2[0].y);
            float fA = sig_fast(acc[1][q]     + bias2[1].x);
            float fB = sig_fast(acc[1][q + 1] + bias2[1].y);
            float gA = tanh_fast(acc[2][q]     + bias2[2].x);
            float gB = tanh_fast(acc[2][q + 1] + bias2[2].y);
            float oA = sig_fast(acc[3][q]     + bias2[3].x);
            float oB = sig_fast(acc[3][q + 1] + bias2[3].y);
            int s = rs * 2;
            float cA = fmaf(fA, cst[s],     iA * gA);
            float cB = fmaf(fB, cst[s + 1], iB * gB);
            cst[s] = cA; cst[s + 1] = cB;
            float hA = oA * tanh_fast(cA);
            float hB = oB * tanh_fast(cB);
            hsum[s] += hA; hsum[s + 1] += hB;
            hv[rs] = pack_bf2(hA, hB);
        }
        {   // one STS.64: this thread's h unit-pair, in A-fragment layout
            char* p = (char*)&hfq[(nxt * 8 + kkp) * 32 + lane] + wordoff;
            u64 pp;
            asm("mov.b64 %0, {%1, %2};" : "=l"(pp) : "r"(hv[0]), "r"(hv[1]));
            asm volatile("st.shared.b64 [%0], %1;"
                         :: "l"(__cvta_generic_to_shared(p)), "l"(pp) : "memory");
        }
        cur = nxt;
    }

#pragma unroll
    for (int rs = 0; rs < 2; rs++) {
        int b = b0 + t4 + 8 * rs;
        *(float2*)&g_rep[b * HH + colbase] = make_float2(hsum[rs * 2], hsum[rs * 2 + 1]);
    }

    // ---------------- fused classifier tail (round-12 cls, inlined) ---------
    __shared__ int s_old;
    __shared__ float part[2][HH];
    __shared__ float mean_s[HH];
    __shared__ float lg[NCLASS];
    int gidx = blockIdx.x >> 1;   // graph id (2 CTAs per graph)
    __syncthreads();              // all g_rep stores of this CTA issued
    if (tid == 0) {
        __threadfence();          // release: g_rep visible before arrival
        s_old = atomicAdd(&g_cnt[gidx], 1);
    }
    __syncthreads();              // s_old uniform across CTA
    if (s_old == 1) {             // second arrival computes cls for this graph
        if (tid == 0) __threadfence();   // acquire (cumulative via syncthreads)
        __syncthreads();
        if (tid < 256) {
            int h = tid & 127, half = tid >> 7;
            float s = 0.f;
#pragma unroll
            for (int c = 0; c < 16; c++)
                s += g_rep[(gidx * NC + half * 16 + c) * HH + h];
            part[half][h] = s;
        }
        __syncthreads();
        if (tid < HH) mean_s[tid] = (part[0][tid] + part[1][tid]) * (1.0f / NC);
        __syncthreads();
        if (tid < NCLASS) {
            float d = b_cls[tid];
            for (int hh = 0; hh < HH; hh++)
                d = fmaf(mean_s[hh], W_cls[tid * HH + hh], d);
            lg[tid] = d;
        }
        __syncthreads();
        if (tid == 0) {
            float mx = lg[0];
            for (int n = 1; n < NCLASS; n++) mx = fmaxf(mx, lg[n]);
            float sum = 0.f;
            for (int n = 0; n < NCLASS; n++) sum += expf(lg[n] - mx);
            float l = logf(sum);
            for (int n = 0; n < NCLASS; n++)
                out[gidx * NCLASS + n] = lg[n] - mx - l;
            g_cnt[gidx] = 0;      // reset for next graph replay
        }
    }
}

extern "C" void kernel_launch(void* const* d_in, const int* in_sizes, int n_in,
                              void* d_out, int out_size) {
    (void)in_sizes; (void)n_in; (void)out_size;
    const float* x     = (const float*)d_in[0];  // cycle_reps [64,32,128,64]
    const float* W_ih  = (const float*)d_in[1];  // [512,64]
    const float* W_hh  = (const float*)d_in[2];  // [512,128]
    const float* b_ih  = (const float*)d_in[3];  // [512]
    const float* b_hh  = (const float*)d_in[4];  // [512]
    const float* W_cls = (const float*)d_in[5];  // [10,128]
    const float* b_cls = (const float*)d_in[6];  // [10]

    cudaFuncSetAttribute(lstm_fused, cudaFuncAttributeMaxDynamicSharedMemorySize, LSM_BYTES);
    lstm_fused<<<128, LTH, LSM_BYTES>>>(x, W_ih, W_hh, b_ih, b_hh,
                                        W_cls, b_cls, (float*)d_out);
}

// round 15
// speedup vs baseline: 1.1864x; 1.0091x over previous
#include <cuda_runtime.h>
#include <cuda_bf16.h>
#include <cstdint>

#define NG 64
#define NC 32
#define LL 128
#define DD 64
#define HH 128
#define NCLASS 10
#define BTOT 2048          // G*C
#define NGATES 512         // 4*H

__device__ float g_rep[BTOT * HH];   // sum_t h (allocation-free scratch)
__device__ int g_cnt[NG];            // per-graph arrival counters (self-resetting)

typedef unsigned long long u64;

__device__ __forceinline__ float tanh_fast(float x) {
    float r;
    asm("tanh.approx.f32 %0, %1;" : "=f"(r) : "f"(x));
    return r;
}
__device__ __forceinline__ float sig_fast(float x) {
    return fmaf(0.5f, tanh_fast(0.5f * x), 0.5f);
}
__device__ __forceinline__ uint32_t pack_bf2(float lo, float hi) {
    __nv_bfloat162 v = __floats2bfloat162_rn(lo, hi);   // .x = lo
    return *(uint32_t*)&v;
}

#define MMA_BF16(acc, a0, a1, a2, a3, bb0, bb1) \
    asm("mma.sync.aligned.m16n8k16.row.col.f32.bf16.bf16.f32 " \
        "{%0,%1,%2,%3}, {%4,%5,%6,%7}, {%8,%9}, {%0,%1,%2,%3};" \
        : "+f"((acc)[0]), "+f"((acc)[1]), "+f"((acc)[2]), "+f"((acc)[3]) \
        : "r"(a0), "r"(a1), "r"(a2), "r"(a3), "r"(bb0), "r"(bb1))

// ============================================================================
// Fused LSTM + classifier tail — round-14 base with ONE isolated change:
// x-chunk staging moves from the TOP of a chunk-boundary iteration (LDG
// latency fully exposed against the very next barrier) to the END of
// iteration t≡14 (staging chunk (t+2)>>4), giving the LDG+cvt+STS chain two
// full barrier phases to drain. The x-GEMM placement, acc lifetime, and all
// other loop code are byte-identical to round 14 (R13's regression is
// attributed to the x-GEMM hoist's acc liveness, not the staging move).
// ============================================================================
#define LTH 512
#define HFQ_O 0                    // [2][8][32] uint4      (8 KB)
#define XFQ_O 512                  // [2][16][4][32] uint4  (64 KB)
#define WIFQ_O (512 + 4096)        // [16][4][2][32] uint4  (64 KB)
#define LSMQ (WIFQ_O + 4096)
#define LSM_BYTES (LSMQ * 16)      // 139264 B

__device__ __forceinline__ void stage_chunk(uint4* xfq, const float* x,
                                            int b0, int chunk,
                                            int s_tl, int s_kk2, int s_j) {
    int cb = chunk & 1;
    const float* p0 = x + (((size_t)(b0 + s_j) * LL) + (chunk * 16 + s_tl)) * DD + s_kk2 * 16;
    const float* p1 = p0 + (size_t)8 * LL * DD;
    float4 r0a = *(const float4*)p0,       r0b = *(const float4*)(p0 + 4);
    float4 r0c = *(const float4*)(p0 + 8), r0d = *(const float4*)(p0 + 12);
    float4 r1a = *(const float4*)p1,       r1b = *(const float4*)(p1 + 4);
    float4 r1c = *(const float4*)(p1 + 8), r1d = *(const float4*)(p1 + 12);
    uint4* dst = &xfq[((cb * 16 + s_tl) * 4 + s_kk2) * 32 + 4 * s_j];
    dst[0] = make_uint4(pack_bf2(r0a.x, r0a.y), pack_bf2(r1a.x, r1a.y),
                        pack_bf2(r0c.x, r0c.y), pack_bf2(r1c.x, r1c.y));
    dst[1] = make_uint4(pack_bf2(r0a.z, r0a.w), pack_bf2(r1a.z, r1a.w),
                        pack_bf2(r0c.z, r0c.w), pack_bf2(r1c.z, r1c.w));
    dst[2] = make_uint4(pack_bf2(r0b.x, r0b.y), pack_bf2(r1b.x, r1b.y),
                        pack_bf2(r0d.x, r0d.y), pack_bf2(r1d.x, r1d.y));
    dst[3] = make_uint4(pack_bf2(r0b.z, r0b.w), pack_bf2(r1b.z, r1b.w),
                        pack_bf2(r0d.z, r0d.w), pack_bf2(r1d.z, r1d.w));
}

__global__ void __launch_bounds__(LTH, 1)
lstm_fused(const float* __restrict__ x, const float* __restrict__ W_ih,
           const float* __restrict__ W_hh,
           const float* __restrict__ b_ih, const float* __restrict__ b_hh,
           const float* __restrict__ W_cls, const float* __restrict__ b_cls,
           float* __restrict__ out) {
    extern __shared__ uint4 smq[];
    uint4* hfq  = smq + HFQ_O;    // [(buf*8+kk)*32 + lane]
    uint4* xfq  = smq + XFQ_O;    // [((buf*16+tl)*4+kk2)*32 + lane]
    uint4* wifq = smq + WIFQ_O;   // [((w*4+kk2)*2+p)*32 + lane]

    int tid = threadIdx.x, lane = tid & 31, w = tid >> 5;   // w in [0,16)
    int t4 = lane >> 2, tm4 = lane & 3;
    int b0 = blockIdx.x * 16;
    int colbase = 8 * w + 2 * tm4;    // unit pair (colbase, colbase+1)

    // W_hh bf16 B-fragments -> registers (one-time). Frag col n = t4.
    uint32_t wb0[8][4], wb1[8][4];
#pragma unroll
    for (int kk = 0; kk < 8; kk++)
#pragma unroll
        for (int g = 0; g < 4; g++) {
            int row = g * HH + 8 * w + t4;
            float2 lo2 = *(const float2*)&W_hh[row * HH + kk * 16 + 2 * tm4];
            float2 hi2 = *(const float2*)&W_hh[row * HH + kk * 16 + 2 * tm4 + 8];
            wb0[kk][g] = pack_bf2(lo2.x, lo2.y);
            wb1[kk][g] = pack_bf2(hi2.x, hi2.y);
        }

    // W_ih bf16 B-fragments -> smem (warp-private region; K=64 -> 4 kk2)
#pragma unroll
    for (int kk2 = 0; kk2 < 4; kk2++) {
        uint32_t bb[4][2];
#pragma unroll
        for (int g = 0; g < 4; g++) {
            int row = g * HH + 8 * w + t4;
            float2 lo2 = *(const float2*)&W_ih[row * DD + kk2 * 16 + 2 * tm4];
            float2 hi2 = *(const float2*)&W_ih[row * DD + kk2 * 16 + 2 * tm4 + 8];
            bb[g][0] = pack_bf2(lo2.x, lo2.y);
            bb[g][1] = pack_bf2(hi2.x, hi2.y);
        }
        wifq[((w * 4 + kk2) * 2 + 0) * 32 + lane] =
            make_uint4(bb[0][0], bb[0][1], bb[1][0], bb[1][1]);
        wifq[((w * 4 + kk2) * 2 + 1) * 32 + lane] =
            make_uint4(bb[2][0], bb[2][1], bb[3][0], bb[3][1]);
    }
    hfq[tid] = make_uint4(0, 0, 0, 0);   // zero h fragments (both buffers)

    const int kkp = w >> 1;              // producer h-store coords
    const int wordoff = 8 * (w & 1);
    const int s_tl = tid >> 5, s_kk2 = (tid >> 3) & 3, s_j = tid & 7;  // x staging

    // Stage x chunk 0 (steps 0..15) before the loop
    stage_chunk(xfq, x, b0, 0, s_tl, s_kk2, s_j);

    float2 bias2[4];
#pragma unroll
    for (int g = 0; g < 4; g++) {
        int c = g * HH + colbase;
        bias2[g] = make_float2(b_ih[c] + b_hh[c], b_ih[c + 1] + b_hh[c + 1]);
    }
    float cst[4], hsum[4];
#pragma unroll
    for (int k = 0; k < 4; k++) { cst[k] = 0.f; hsum[k] = 0.f; }

    int cur = 0;
#pragma unroll 1
    for (int t = 0; t < LL; t++) {
        __syncthreads();   // h[cur] stores (prev step) + staged chunk visible

        float acc[4][4];
#pragma unroll
        for (int g = 0; g < 4; g++)
#pragma unroll
            for (int q = 0; q < 4; q++) acc[g][q] = 0.f;

        // Recurrence: h_{t-1} @ W_hh^T (W_hh in registers)
#pragma unroll
        for (int kk = 0; kk < 8; kk++) {
            uint4 aq = hfq[(cur * 8 + kk) * 32 + lane];
            MMA_BF16(acc[0], aq.x, aq.y, aq.z, aq.w, wb0[kk][0], wb1[kk][0]);
            MMA_BF16(acc[1], aq.x, aq.y, aq.z, aq.w, wb0[kk][1], wb1[kk][1]);
            MMA_BF16(acc[2], aq.x, aq.y, aq.z, aq.w, wb0[kk][2], wb1[kk][2]);
            MMA_BF16(acc[3], aq.x, aq.y, aq.z, aq.w, wb0[kk][3], wb1[kk][3]);
        }
        // Input GEMM: x[:,t,:] @ W_ih^T (fused into same accumulators)
        {
            int cb = (t >> 4) & 1, tl = t & 15;
#pragma unroll
            for (int kk2 = 0; kk2 < 4; kk2++) {
                uint4 aq = xfq[((cb * 16 + tl) * 4 + kk2) * 32 + lane];
                uint4 q0 = wifq[((w * 4 + kk2) * 2 + 0) * 32 + lane];
                uint4 q1 = wifq[((w * 4 + kk2) * 2 + 1) * 32 + lane];
                MMA_BF16(acc[0], aq.x, aq.y, aq.z, aq.w, q0.x, q0.y);
                MMA_BF16(acc[1], aq.x, aq.y, aq.z, aq.w, q0.z, q0.w);
                MMA_BF16(acc[2], aq.x, aq.y, aq.z, aq.w, q1.x, q1.y);
                MMA_BF16(acc[3], aq.x, aq.y, aq.z, aq.w, q1.z, q1.w);
            }
        }

        int nxt = cur ^ 1;
        uint32_t hv[2];
#pragma unroll
        for (int rs = 0; rs < 2; rs++) {
            int q = rs * 2;   // C-frag: q0,q1 = row t4; q2,q3 = row t4+8
            float iA = sig_fast(acc[0][q]     + bias2[0].x);
            float iB = sig_fast(acc[0][q + 1] + bias2[0].y);
            float fA = sig_fast(acc[1][q]     + bias2[1].x);
            float fB = sig_fast(acc[1][q + 1] + bias2[1].y);
            float gA = tanh_fast(acc[2][q]     + bias2[2].x);
            float gB = tanh_fast(acc[2][q + 1] + bias2[2].y);
            float oA = sig_fast(acc[3][q]     + bias2[3].x);
            float oB = sig_fast(acc[3][q + 1] + bias2[3].y);
            int s = rs * 2;
            float cA = fmaf(fA, cst[s],     iA * gA);
            float cB = fmaf(fB, cst[s + 1], iB * gB);
            cst[s] = cA; cst[s + 1] = cB;
            float hA = oA * tanh_fast(cA);
            float hB = oB * tanh_fast(cB);
            hsum[s] += hA; hsum[s + 1] += hB;
            hv[rs] = pack_bf2(hA, hB);
        }
        {   // one STS.64: this thread's h unit-pair, in A-fragment layout
            char* p = (char*)&hfq[(nxt * 8 + kkp) * 32 + lane] + wordoff;
            u64 pp;
            asm("mov.b64 %0, {%1, %2};" : "=l"(pp) : "r"(hv[0]), "r"(hv[1]));
            asm volatile("st.shared.b64 [%0], %1;"
                         :: "l"(__cvta_generic_to_shared(p)), "l"(pp) : "memory");
        }

        // Stage chunk (t+2)>>4 at end of iteration t (t≡14): two barrier
        // phases separate these STS from their first LDS; LDG latency hidden.
        if ((t & 15) == 14 && t + 2 < LL)
            stage_chunk(xfq, x, b0, (t + 2) >> 4, s_tl, s_kk2, s_j);

        cur = nxt;
    }

#pragma unroll
    for (int rs = 0; rs < 2; rs++) {
        int b = b0 + t4 + 8 * rs;
        *(float2*)&g_rep[b * HH + colbase] = make_float2(hsum[rs * 2], hsum[rs * 2 + 1]);
    }

    // ---------------- fused classifier tail (round-14, unchanged) -----------
    __shared__ int s_old;
    __shared__ float part[2][HH];
    __shared__ float mean_s[HH];
    __shared__ float lg[NCLASS];
    int gidx = blockIdx.x >> 1;   // graph id (2 CTAs per graph)
    __syncthreads();              // all g_rep stores of this CTA issued
    if (tid == 0) {
        __threadfence();          // release: g_rep visible before arrival
        s_old = atomicAdd(&g_cnt[gidx], 1);
    }
    __syncthreads();              // s_old uniform across CTA
    if (s_old == 1) {             // second arrival computes cls for this graph
        if (tid == 0) __threadfence();   // acquire
        __syncthreads();
        if (tid < 256) {
            int h = tid & 127, half = tid >> 7;
            float s = 0.f;
#pragma unroll
            for (int c = 0; c < 16; c++)
                s += g_rep[(gidx * NC + half * 16 + c) * HH + h];
            part[half][h] = s;
        }
        __syncthreads();
        if (tid < HH) mean_s[tid] = (part[0][tid] + part[1][tid]) * (1.0f / NC);
        __syncthreads();
        if (tid < NCLASS) {
            float d = b_cls[tid];
            for (int hh = 0; hh < HH; hh++)
                d = fmaf(mean_s[hh], W_cls[tid * HH + hh], d);
            lg[tid] = d;
        }
        __syncthreads();
        if (tid == 0) {
            float mx = lg[0];
            for (int n = 1; n < NCLASS; n++) mx = fmaxf(mx, lg[n]);
            float sum = 0.f;
            for (int n = 0; n < NCLASS; n++) sum += expf(lg[n] - mx);
            float l = logf(sum);
            for (int n = 0; n < NCLASS; n++)
                out[gidx * NCLASS + n] = lg[n] - mx - l;
            g_cnt[gidx] = 0;      // reset for next graph replay
        }
    }
}

extern "C" void kernel_launch(void* const* d_in, const int* in_sizes, int n_in,
                              void* d_out, int out_size) {
    (void)in_sizes; (void)n_in; (void)out_size;
    const float* x     = (const float*)d_in[0];  // cycle_reps [64,32,128,64]
    const float* W_ih  = (const float*)d_in[1];  // [512,64]
    const float* W_hh  = (const float*)d_in[2];  // [512,128]
    const float* b_ih  = (const float*)d_in[3];  // [512]
    const float* b_hh  = (const float*)d_in[4];  // [512]
    const float* W_cls = (const float*)d_in[5];  // [10,128]
    const float* b_cls = (const float*)d_in[6];  // [10]

    cudaFuncSetAttribute(lstm_fused, cudaFuncAttributeMaxDynamicSharedMemorySize, LSM_BYTES);
    lstm_fused<<<128, LTH, LSM_BYTES>>>(x, W_ih, W_hh, b_ih, b_hh,
                                        W_cls, b_cls, (float*)d_out);
}